// round 1
// baseline (speedup 1.0000x reference)
#include <cuda_runtime.h>
#include <cstdint>

#define S_  2048
#define N_  8
#define E_  512
#define C_  1024
#define G_  32
#define CG_ 32
#define M_  (S_ * N_)   // 16384 tokens

// ---------------- scratch (no allocations allowed) ----------------
__device__ float    g_logits[(size_t)M_ * C_];   // 64 MB
__device__ float    g_W2T[(size_t)C_ * E_];      // 2 MB, W2 transposed [c][e]
__device__ unsigned g_idx[(size_t)M_ * G_];      // packed (a1 | a2<<8 | ui<<16)

// ---------------- packed f32x2 helpers (sm_103a FFMA2 path) ----------------
__device__ __forceinline__ unsigned long long pack_ff(float lo, float hi) {
    unsigned long long r;
    asm("mov.b64 %0, {%1, %2};" : "=l"(r) : "f"(lo), "f"(hi));
    return r;
}
__device__ __forceinline__ unsigned long long fma2(unsigned long long a,
                                                   unsigned long long b,
                                                   unsigned long long c) {
    unsigned long long d;
    asm("fma.rn.f32x2 %0, %1, %2, %3;" : "=l"(d) : "l"(a), "l"(b), "l"(c));
    return d;
}

// ---------------- kernel 1: transpose W2 (E,C) -> W2T (C,E) ----------------
__global__ void transpose_kernel(const float* __restrict__ W2) {
    __shared__ float tile[32][33];
    const int c0 = blockIdx.x * 32;
    const int e0 = blockIdx.y * 32;
    const int tx = threadIdx.x;   // 32
    const int ty = threadIdx.y;   // 8
#pragma unroll
    for (int r = 0; r < 32; r += 8)
        tile[ty + r][tx] = W2[(size_t)(e0 + ty + r) * C_ + c0 + tx];
    __syncthreads();
#pragma unroll
    for (int r = 0; r < 32; r += 8)
        g_W2T[(size_t)(c0 + ty + r) * E_ + e0 + tx] = tile[tx][ty + r];
}

// ---------------- kernel 2: fp32 GEMM (f32x2 packed) with epilogue ----------
// logits[m,c] = 3 * (sum_k x[m,k] * W1[c,k]) + (3*b1[c] + class_offsets[c])
__global__ __launch_bounds__(256, 2)
void gemm3_kernel(const float* __restrict__ A,   // x  [M, K]
                  const float* __restrict__ B,   // W1 [C, K]
                  const float* __restrict__ b1,
                  const float* __restrict__ coff) {
    const int K = E_;
    __shared__ float As[16][128];
    __shared__ float Bs[16][128];

    const int tid  = threadIdx.x;
    const int bm   = blockIdx.y * 128;
    const int bn   = blockIdx.x * 128;
    const int tm   = (tid >> 4) << 3;
    const int tn   = (tid & 15) << 3;
    const int lrow = tid >> 2;          // 0..63
    const int lc4  = (tid & 3) << 2;    // 0,4,8,12

    const float* Ap = A + (size_t)(bm + lrow) * K + lc4;
    const float* Bp = B + (size_t)(bn + lrow) * K + lc4;

    unsigned long long acc[8][4];
#pragma unroll
    for (int i = 0; i < 8; i++)
#pragma unroll
        for (int j = 0; j < 4; j++) acc[i][j] = 0ULL;

    // prefetch first tile
    float4 ra0 = *(const float4*)(Ap);
    float4 ra1 = *(const float4*)(Ap + 64 * K);
    float4 rb0 = *(const float4*)(Bp);
    float4 rb1 = *(const float4*)(Bp + 64 * K);

    for (int k0 = 0; k0 < K; k0 += 16) {
        As[lc4 + 0][lrow]      = ra0.x; As[lc4 + 1][lrow]      = ra0.y;
        As[lc4 + 2][lrow]      = ra0.z; As[lc4 + 3][lrow]      = ra0.w;
        As[lc4 + 0][lrow + 64] = ra1.x; As[lc4 + 1][lrow + 64] = ra1.y;
        As[lc4 + 2][lrow + 64] = ra1.z; As[lc4 + 3][lrow + 64] = ra1.w;
        Bs[lc4 + 0][lrow]      = rb0.x; Bs[lc4 + 1][lrow]      = rb0.y;
        Bs[lc4 + 2][lrow]      = rb0.z; Bs[lc4 + 3][lrow]      = rb0.w;
        Bs[lc4 + 0][lrow + 64] = rb1.x; Bs[lc4 + 1][lrow + 64] = rb1.y;
        Bs[lc4 + 2][lrow + 64] = rb1.z; Bs[lc4 + 3][lrow + 64] = rb1.w;
        __syncthreads();

        if (k0 + 16 < K) {                 // prefetch next tile under compute
            ra0 = *(const float4*)(Ap + k0 + 16);
            ra1 = *(const float4*)(Ap + 64 * K + k0 + 16);
            rb0 = *(const float4*)(Bp + k0 + 16);
            rb1 = *(const float4*)(Bp + 64 * K + k0 + 16);
        }

#pragma unroll
        for (int kk = 0; kk < 16; kk++) {
            float4 av0 = *(const float4*)&As[kk][tm];
            float4 av1 = *(const float4*)&As[kk][tm + 4];
            ulonglong2 bv0 = *(const ulonglong2*)&Bs[kk][tn];
            ulonglong2 bv1 = *(const ulonglong2*)&Bs[kk][tn + 4];
            float a_[8] = {av0.x, av0.y, av0.z, av0.w,
                           av1.x, av1.y, av1.z, av1.w};
#pragma unroll
            for (int i = 0; i < 8; i++) {
                unsigned long long ad = pack_ff(a_[i], a_[i]);
                acc[i][0] = fma2(ad, bv0.x, acc[i][0]);
                acc[i][1] = fma2(ad, bv0.y, acc[i][1]);
                acc[i][2] = fma2(ad, bv1.x, acc[i][2]);
                acc[i][3] = fma2(ad, bv1.y, acc[i][3]);
            }
        }
        __syncthreads();
    }

    // epilogue
    float cb[8];
#pragma unroll
    for (int j = 0; j < 8; j++) {
        int c = bn + tn + j;
        cb[j] = 3.0f * b1[c] + coff[c];
    }
#pragma unroll
    for (int i = 0; i < 8; i++) {
        float o[8];
#pragma unroll
        for (int j = 0; j < 4; j++) {
            float lo = __uint_as_float((unsigned)(acc[i][j] & 0xFFFFFFFFu));
            float hi = __uint_as_float((unsigned)(acc[i][j] >> 32));
            o[2 * j]     = 3.0f * lo + cb[2 * j];
            o[2 * j + 1] = 3.0f * hi + cb[2 * j + 1];
        }
        float* outp = g_logits + (size_t)(bm + tm + i) * C_ + bn + tn;
        *(float4*)(outp)     = make_float4(o[0], o[1], o[2], o[3]);
        *(float4*)(outp + 4) = make_float4(o[4], o[5], o[6], o[7]);
    }
}

// ---------------- kernel 3: per-group softmax + Gumbel argmax + sample ------
__global__ __launch_bounds__(256)
void sample_kernel(const float* __restrict__ g1,
                   const float* __restrict__ g2,
                   const float* __restrict__ w_interp,
                   const float* __restrict__ u_interp,
                   float* __restrict__ outSampled,
                   float* __restrict__ outSoft) {
    const int t = blockIdx.x * 256 + threadIdx.x;   // [0, M_*G_)
    const float* lg = g_logits + (size_t)t * CG_;

    float v[32];
#pragma unroll
    for (int q = 0; q < 8; q++) {
        float4 x4 = *(const float4*)(lg + q * 4);
        v[q * 4 + 0] = x4.x; v[q * 4 + 1] = x4.y;
        v[q * 4 + 2] = x4.z; v[q * 4 + 3] = x4.w;
    }

    float mx = v[0];
#pragma unroll
    for (int i = 1; i < 32; i++) mx = fmaxf(mx, v[i]);

    float e[32];
    float sum = 0.0f;
#pragma unroll
    for (int i = 0; i < 32; i++) { e[i] = __expf(v[i] - mx); sum += e[i]; }
    const float inv = 1.0f / sum;

    float* so = outSoft + (size_t)t * CG_;
#pragma unroll
    for (int q = 0; q < 8; q++) {
        *(float4*)(so + q * 4) = make_float4(e[q * 4 + 0] * inv, e[q * 4 + 1] * inv,
                                             e[q * 4 + 2] * inv, e[q * 4 + 3] * inv);
    }

    // argmax(lg + g1), argmax(lg + g2); strictly-greater => first max (JAX tie rule)
    const float* gp1 = g1 + (size_t)t * CG_;
    const float* gp2 = g2 + (size_t)t * CG_;
    int a1 = 0, a2 = 0;
    float bb1 = -3.4e38f, bb2 = -3.4e38f;
#pragma unroll
    for (int q = 0; q < 8; q++) {
        float4 gg = *(const float4*)(gp1 + q * 4);
        float c0 = v[q * 4 + 0] + gg.x, c1 = v[q * 4 + 1] + gg.y;
        float c2 = v[q * 4 + 2] + gg.z, c3 = v[q * 4 + 3] + gg.w;
        if (c0 > bb1) { bb1 = c0; a1 = q * 4 + 0; }
        if (c1 > bb1) { bb1 = c1; a1 = q * 4 + 1; }
        if (c2 > bb1) { bb1 = c2; a1 = q * 4 + 2; }
        if (c3 > bb1) { bb1 = c3; a1 = q * 4 + 3; }
    }
#pragma unroll
    for (int q = 0; q < 8; q++) {
        float4 gg = *(const float4*)(gp2 + q * 4);
        float c0 = v[q * 4 + 0] + gg.x, c1 = v[q * 4 + 1] + gg.y;
        float c2 = v[q * 4 + 2] + gg.z, c3 = v[q * 4 + 3] + gg.w;
        if (c0 > bb2) { bb2 = c0; a2 = q * 4 + 0; }
        if (c1 > bb2) { bb2 = c1; a2 = q * 4 + 1; }
        if (c2 > bb2) { bb2 = c2; a2 = q * 4 + 2; }
        if (c3 > bb2) { bb2 = c3; a2 = q * 4 + 3; }
    }

    const float w  = w_interp[t];
    const float u  = u_interp[t];
    const bool  ui = (u < 1.0f);              // INTERP_PROB = 1.0
    const float wa = ui ? w : 1.0f;
    const float wb = ui ? (1.0f - w) : 0.0f;

    float* sp = outSampled + (size_t)t * CG_;
#pragma unroll
    for (int q = 0; q < 8; q++) {
        float o[4];
#pragma unroll
        for (int k = 0; k < 4; k++) {
            int i = q * 4 + k;
            float val = 0.0f;
            if (i == a1) val += wa;
            if (i == a2) val += wb;
            o[k] = val;
        }
        *(float4*)(sp + q * 4) = make_float4(o[0], o[1], o[2], o[3]);
    }

    g_idx[t] = (unsigned)a1 | ((unsigned)a2 << 8) | (ui ? 0x10000u : 0u);
}

// ---------------- kernel 4: sparse projection + LayerNorm -> pos, neg -------
__global__ __launch_bounds__(128)
void proj_ln_kernel(const float* __restrict__ w_interp,
                    const float* __restrict__ b2,
                    const float* __restrict__ gamma,
                    const float* __restrict__ beta,
                    float* __restrict__ outPos,
                    float* __restrict__ outNeg) {
    const int tok = blockIdx.x;
    const int tid = threadIdx.x;   // 128 threads, 4 e's each
    __shared__ unsigned sidx[32];
    __shared__ float    sw[32];
    __shared__ float    red1[4], red2[4];

    if (tid < 32) {
        sidx[tid] = g_idx[(size_t)tok * G_ + tid];
        sw[tid]   = w_interp[(size_t)tok * G_ + tid];
    }
    __syncthreads();

    const int e4 = tid * 4;
    float4 bb = *(const float4*)(b2 + e4);
    float hx = bb.x, hy = bb.y, hz = bb.z, hw = bb.w;

#pragma unroll
    for (int g = 0; g < 32; g++) {
        const unsigned p = sidx[g];
        const float w = sw[g];
        const bool ui = (p & 0x10000u) != 0u;
        const int a1 = p & 255;
        const int a2 = (p >> 8) & 255;
        const float wa = ui ? w : 1.0f;
        const float wb = ui ? (1.0f - w) : 0.0f;
        const float4 r1 = *(const float4*)&g_W2T[(size_t)(g * CG_ + a1) * E_ + e4];
        const float4 r2 = *(const float4*)&g_W2T[(size_t)(g * CG_ + a2) * E_ + e4];
        hx += wa * r1.x + wb * r2.x;
        hy += wa * r1.y + wb * r2.y;
        hz += wa * r1.z + wb * r2.z;
        hw += wa * r1.w + wb * r2.w;
    }

    // LayerNorm over E_=512
    float s1 = hx + hy + hz + hw;
    float s2 = hx * hx + hy * hy + hz * hz + hw * hw;
#pragma unroll
    for (int off = 16; off > 0; off >>= 1) {
        s1 += __shfl_xor_sync(0xFFFFFFFFu, s1, off);
        s2 += __shfl_xor_sync(0xFFFFFFFFu, s2, off);
    }
    const int wid = tid >> 5, lid = tid & 31;
    if (lid == 0) { red1[wid] = s1; red2[wid] = s2; }
    __syncthreads();
    s1 = red1[0] + red1[1] + red1[2] + red1[3];
    s2 = red2[0] + red2[1] + red2[2] + red2[3];

    const float mean = s1 * (1.0f / (float)E_);
    const float var  = s2 * (1.0f / (float)E_) - mean * mean;
    const float rstd = rsqrtf(var + 1e-5f);

    const float4 gm = *(const float4*)(gamma + e4);
    const float4 bt = *(const float4*)(beta + e4);
    float4 o;
    o.x = (hx - mean) * rstd * gm.x + bt.x;
    o.y = (hy - mean) * rstd * gm.y + bt.y;
    o.z = (hz - mean) * rstd * gm.z + bt.z;
    o.w = (hw - mean) * rstd * gm.w + bt.w;

    *(float4*)(outPos + (size_t)tok * E_ + e4) = o;
    *(float4*)(outNeg + (size_t)tok * E_ + e4) = o;   // rev fwd == sampled => neg == pos
}

// ---------------- launch ----------------
extern "C" void kernel_launch(void* const* d_in, const int* in_sizes, int n_in,
                              void* d_out, int out_size) {
    const float* x     = (const float*)d_in[0];
    const float* W1    = (const float*)d_in[1];
    const float* b1    = (const float*)d_in[2];
    const float* coff  = (const float*)d_in[3];
    const float* W2    = (const float*)d_in[4];
    const float* b2    = (const float*)d_in[5];
    const float* gamma = (const float*)d_in[6];
    const float* beta  = (const float*)d_in[7];
    const float* g1    = (const float*)d_in[8];
    const float* g2    = (const float*)d_in[9];
    const float* wi    = (const float*)d_in[10];
    const float* ui    = (const float*)d_in[11];

    float* out        = (float*)d_out;
    float* outSampled = out;
    float* outSoft    = out + (size_t)M_ * C_;
    float* outPos     = out + 2 * (size_t)M_ * C_;
    float* outNeg     = outPos + (size_t)M_ * E_;

    transpose_kernel<<<dim3(C_ / 32, E_ / 32), dim3(32, 8)>>>(W2);
    gemm3_kernel<<<dim3(C_ / 128, M_ / 128), 256>>>(x, W1, b1, coff);
    sample_kernel<<<(M_ * G_) / 256, 256>>>(g1, g2, wi, ui, outSampled, outSoft);
    proj_ln_kernel<<<M_, 128>>>(wi, b2, gamma, beta, outPos, outNeg);
}

// round 4
// speedup vs baseline: 1.2531x; 1.2531x over previous
#include <cuda_runtime.h>
#include <cuda_fp16.h>
#include <cstdint>

#define S_  2048
#define N_  8
#define E_  512
#define C_  1024
#define G_  32
#define CG_ 32
#define M_  (S_ * N_)        // 16384 tokens
#define R_  (M_ + C_)        // 17408 rows (x rows then W1 rows)
#define TAU_ 1e-4f

// ---------------- scratch (no allocations allowed) ----------------
__device__ __half g_h1[(size_t)R_ * E_];     // fp16 split hi  (W1 rows pre-scaled x64)
__device__ __half g_h2[(size_t)R_ * E_];     // fp16 split lo
__device__ float    g_W2T[(size_t)C_ * E_];  // W2 transposed [c][e]
__device__ unsigned g_idx[(size_t)M_ * G_];  // packed (a1 | a2<<8 | ui<<16)

// ---------------- PTX helpers (all base sm_103 legal) ----------------
__device__ __forceinline__ uint32_t smem_u32(const void* p) {
    uint32_t a;
    asm("{ .reg .u64 t; cvta.to.shared.u64 t, %1; cvt.u32.u64 %0, t; }"
        : "=r"(a) : "l"(p));
    return a;
}
__device__ __forceinline__ void ldsm_x4(uint32_t& r0, uint32_t& r1,
                                        uint32_t& r2, uint32_t& r3, uint32_t addr) {
    asm volatile("ldmatrix.sync.aligned.m8n8.x4.shared.b16 {%0,%1,%2,%3}, [%4];"
                 : "=r"(r0), "=r"(r1), "=r"(r2), "=r"(r3) : "r"(addr));
}
__device__ __forceinline__ void mma16816(float* d, const uint32_t* a, const uint32_t* b) {
    asm volatile(
        "mma.sync.aligned.m16n8k16.row.col.f32.f16.f16.f32 "
        "{%0,%1,%2,%3},{%4,%5,%6,%7},{%8,%9},{%0,%1,%2,%3};"
        : "+f"(d[0]), "+f"(d[1]), "+f"(d[2]), "+f"(d[3])
        : "r"(a[0]), "r"(a[1]), "r"(a[2]), "r"(a[3]), "r"(b[0]), "r"(b[1]));
}
#define CP16(dst, src) \
    asm volatile("cp.async.cg.shared.global [%0], [%1], 16;" :: "r"(dst), "l"(src))
#define CP_COMMIT() asm volatile("cp.async.commit_group;" ::: "memory")

// ---------------- kernel 1: transpose W2 (E,C) -> W2T (C,E) ----------------
__global__ void transpose_kernel(const float* __restrict__ W2) {
    __shared__ float tile[32][33];
    const int c0 = blockIdx.x * 32;
    const int e0 = blockIdx.y * 32;
    const int tx = threadIdx.x, ty = threadIdx.y;
#pragma unroll
    for (int r = 0; r < 32; r += 8)
        tile[ty + r][tx] = W2[(size_t)(e0 + ty + r) * C_ + c0 + tx];
    __syncthreads();
#pragma unroll
    for (int r = 0; r < 32; r += 8)
        g_W2T[(size_t)(c0 + ty + r) * E_ + e0 + tx] = tile[tx][ty + r];
}

// ---------------- kernel 2: fp32 -> fp16x2 splits of [x ; 64*W1] ------------
__global__ __launch_bounds__(256)
void split_kernel(const float* __restrict__ x, const float* __restrict__ W1) {
    const size_t i = ((size_t)blockIdx.x * 256 + threadIdx.x) * 8;
    const size_t r = i >> 9;                      // row (512 elems/row)
    const float sc = (r < (size_t)M_) ? 1.0f : 64.0f;
    const float* src = (r < (size_t)M_) ? (x + i) : (W1 + (i - (size_t)M_ * E_));
    const float4 a = ((const float4*)src)[0];
    const float4 b = ((const float4*)src)[1];
    float v[8] = {a.x, a.y, a.z, a.w, b.x, b.y, b.z, b.w};
    __align__(16) __half h1[8], h2[8];
#pragma unroll
    for (int e = 0; e < 8; e++) {
        const float t = v[e] * sc;
        const __half c1 = __float2half_rn(t);
        const float r1 = t - __half2float(c1);
        h1[e] = c1;
        h2[e] = __float2half_rn(r1);
    }
    *reinterpret_cast<uint4*>(&g_h1[i]) = *reinterpret_cast<const uint4*>(h1);
    *reinterpret_cast<uint4*>(&g_h2[i]) = *reinterpret_cast<const uint4*>(h2);
}

// ---------------- kernel 3: fp16x2 mma.sync GEMM + fused softmax/sample -----
#define BK        32
#define BUF_SZ    (128 * 40 * 2)           // 10240 B per buffer (80 B/row padded)
#define STAGE_SZ  (4 * BUF_SZ)             // A1,A2,B1,B2 = 40960 B
#define SMEM_BYTES (3 * STAGE_SZ)          // 122880 B
#define NST       (E_ / BK)                // 16 k-stages
#define CS        132                      // C smem stride (floats)
#define SCALE_    (3.0f / 64.0f)

__device__ __forceinline__ void load_stage(uint32_t sb, int tid, int bm, int bn,
                                           int s, int buf) {
    const uint32_t stage = sb + buf * STAGE_SZ;
    const size_t kofs = (size_t)s * BK;
#pragma unroll
    for (int it = 0; it < 2; it++) {
        const int o = tid + it * 256;           // 0..511
        const int row = o >> 2, ch = o & 3;
        const uint32_t dst = row * 80 + ch * 16;
        const size_t asrc = (size_t)(bm + row) * E_ + kofs + ch * 8;
        const size_t bsrc = (size_t)(M_ + bn + row) * E_ + kofs + ch * 8;
        CP16(stage + dst,                g_h1 + asrc);
        CP16(stage + BUF_SZ + dst,       g_h2 + asrc);
        CP16(stage + 2 * BUF_SZ + dst,   g_h1 + bsrc);
        CP16(stage + 3 * BUF_SZ + dst,   g_h2 + bsrc);
    }
}

// exact-R1 arithmetic dot (sequential fp32 fmaf, k ascending)
__device__ __noinline__ float exact_logit(const float* __restrict__ xr,
                                          const float* __restrict__ wr,
                                          float cbv) {
    float acc = 0.0f;
#pragma unroll 4
    for (int k = 0; k < E_; k++) acc = fmaf(xr[k], wr[k], acc);
    return fmaf(3.0f, acc, cbv);
}

__global__ __launch_bounds__(256, 1)
void gemm_fused_kernel(const float* __restrict__ xg,
                       const float* __restrict__ W1g,
                       const float* __restrict__ b1,
                       const float* __restrict__ coff,
                       const float* __restrict__ g1,
                       const float* __restrict__ g2,
                       const float* __restrict__ w_interp,
                       const float* __restrict__ u_interp,
                       float* __restrict__ outSampled,
                       float* __restrict__ outSoft) {
    extern __shared__ char smem[];
    __shared__ float cb[128];
    const int tid  = threadIdx.x;
    const int lane = tid & 31;
    const int wid  = tid >> 5;
    const int bn   = blockIdx.x * 128;
    const int bm   = blockIdx.y * 128;
    const uint32_t sb = smem_u32(smem);

    if (tid < 128) cb[tid] = 3.0f * b1[bn + tid] + coff[bn + tid];

    // warp tiling: 2 (m) x 4 (n); warp tile m64 x n32
    const int m0 = (wid >> 2) * 64;
    const int n0 = (wid & 3) * 32;
    const int lrow = lane & 7;
    const int lmat = lane >> 3;

    float acc[4][4][4];
#pragma unroll
    for (int i = 0; i < 4; i++)
#pragma unroll
        for (int j = 0; j < 4; j++)
#pragma unroll
            for (int k = 0; k < 4; k++) acc[i][j][k] = 0.0f;

    load_stage(sb, tid, bm, bn, 0, 0); CP_COMMIT();
    load_stage(sb, tid, bm, bn, 1, 1); CP_COMMIT();

#pragma unroll 1
    for (int s = 0; s < NST; s++) {
        if (s + 2 < NST) { load_stage(sb, tid, bm, bn, s + 2, (s + 2) % 3); CP_COMMIT(); }
        if      (s < NST - 2) asm volatile("cp.async.wait_group 2;" ::: "memory");
        else if (s < NST - 1) asm volatile("cp.async.wait_group 1;" ::: "memory");
        else                  asm volatile("cp.async.wait_group 0;" ::: "memory");
        __syncthreads();

        const uint32_t stage = sb + (s % 3) * STAGE_SZ;
        const uint32_t A1 = stage,            A2 = stage + BUF_SZ;
        const uint32_t B1 = stage + 2*BUF_SZ, B2 = stage + 3*BUF_SZ;

#pragma unroll
        for (int kk = 0; kk < BK; kk += 16) {
            uint32_t a1f[4][4], a2f[4][4], b1f[8], b2f[8];
#pragma unroll
            for (int mt = 0; mt < 4; mt++) {
                const int row = m0 + mt * 16 + (lmat & 1) * 8 + lrow;
                const int col = kk + (lmat >> 1) * 8;
                const uint32_t off = row * 80 + col * 2;
                ldsm_x4(a1f[mt][0], a1f[mt][1], a1f[mt][2], a1f[mt][3], A1 + off);
                ldsm_x4(a2f[mt][0], a2f[mt][1], a2f[mt][2], a2f[mt][3], A2 + off);
            }
#pragma unroll
            for (int j = 0; j < 2; j++) {
                const int row = n0 + j * 16 + (lmat >> 1) * 8 + lrow;
                const int col = kk + (lmat & 1) * 8;
                const uint32_t off = row * 80 + col * 2;
                ldsm_x4(b1f[j*4+0], b1f[j*4+1], b1f[j*4+2], b1f[j*4+3], B1 + off);
                ldsm_x4(b2f[j*4+0], b2f[j*4+1], b2f[j*4+2], b2f[j*4+3], B2 + off);
            }
#pragma unroll
            for (int mt = 0; mt < 4; mt++)
#pragma unroll
                for (int nt = 0; nt < 4; nt++) {
                    const int bb = (nt >> 1) * 4 + (nt & 1) * 2;
                    mma16816(acc[mt][nt], a1f[mt], &b1f[bb]);   // x1*w1
                    mma16816(acc[mt][nt], a1f[mt], &b2f[bb]);   // x1*w2
                    mma16816(acc[mt][nt], a2f[mt], &b1f[bb]);   // x2*w1
                }
        }
        __syncthreads();
    }

    // ------- write accums to smem C (reuse stage memory) -------
    float* Cs = (float*)smem;
    const int crow = lane >> 2;
    const int ccol = (lane & 3) * 2;
#pragma unroll
    for (int mt = 0; mt < 4; mt++)
#pragma unroll
        for (int nt = 0; nt < 4; nt++) {
            const int r = m0 + mt * 16 + crow;
            const int c = n0 + nt * 8 + ccol;
            *(float2*)&Cs[(size_t)r * CS + c]       = make_float2(acc[mt][nt][0], acc[mt][nt][1]);
            *(float2*)&Cs[(size_t)(r + 8) * CS + c] = make_float2(acc[mt][nt][2], acc[mt][nt][3]);
        }
    __syncthreads();

    // ------- fused epilogue: per (token, group) softmax + guarded sample -----
#pragma unroll 1
    for (int rep = 0; rep < 2; rep++) {
        const int p  = rep * 256 + tid;     // 0..511
        const int tl = p >> 2;              // token local 0..127
        const int g4 = p & 3;               // group within block 0..3
        const int token = bm + tl;
        const float* cp = &Cs[(size_t)tl * CS + g4 * 32];

        float v[32];
#pragma unroll
        for (int q = 0; q < 8; q++) {
            const float4 c4 = *(const float4*)(cp + q * 4);
            v[q*4+0] = SCALE_ * c4.x + cb[g4*32 + q*4+0];
            v[q*4+1] = SCALE_ * c4.y + cb[g4*32 + q*4+1];
            v[q*4+2] = SCALE_ * c4.z + cb[g4*32 + q*4+2];
            v[q*4+3] = SCALE_ * c4.w + cb[g4*32 + q*4+3];
        }

        float mx = v[0];
#pragma unroll
        for (int i = 1; i < 32; i++) mx = fmaxf(mx, v[i]);
        float e[32], sum = 0.0f;
#pragma unroll
        for (int i = 0; i < 32; i++) { e[i] = __expf(v[i] - mx); sum += e[i]; }
        const float inv = 1.0f / sum;

        float* so = outSoft + (size_t)token * C_ + bn + g4 * 32;
#pragma unroll
        for (int q = 0; q < 8; q++)
            *(float4*)(so + q * 4) = make_float4(e[q*4+0]*inv, e[q*4+1]*inv,
                                                 e[q*4+2]*inv, e[q*4+3]*inv);

        const int gid = (bn >> 5) + g4;
        const size_t gbase = ((size_t)token * G_ + gid) * CG_;
        const float* gp1 = g1 + gbase;
        const float* gp2 = g2 + gbase;

        // ---- draw 1: top-2 tracked argmax ----
        int a1 = 0; float t11 = -3.4e38f, t12 = -3.4e38f;
#pragma unroll
        for (int q = 0; q < 8; q++) {
            const float4 gg = *(const float4*)(gp1 + q * 4);
            const float cc[4] = {v[q*4+0] + gg.x, v[q*4+1] + gg.y,
                                 v[q*4+2] + gg.z, v[q*4+3] + gg.w};
#pragma unroll
            for (int k = 0; k < 4; k++) {
                if (cc[k] > t11) { t12 = t11; t11 = cc[k]; a1 = q*4+k; }
                else if (cc[k] > t12) { t12 = cc[k]; }
            }
        }
        // ---- draw 2 ----
        int a2 = 0; float t21 = -3.4e38f, t22 = -3.4e38f;
#pragma unroll
        for (int q = 0; q < 8; q++) {
            const float4 gg = *(const float4*)(gp2 + q * 4);
            const float cc[4] = {v[q*4+0] + gg.x, v[q*4+1] + gg.y,
                                 v[q*4+2] + gg.z, v[q*4+3] + gg.w};
#pragma unroll
            for (int k = 0; k < 4; k++) {
                if (cc[k] > t21) { t22 = t21; t21 = cc[k]; a2 = q*4+k; }
                else if (cc[k] > t22) { t22 = cc[k]; }
            }
        }

        // ---- exact-rescue guard (rare; replicates R1 fp32 arithmetic) ----
        if (t11 - t12 < TAU_ || t21 - t22 < TAU_) {
            const float* xr = xg + (size_t)token * E_;
            if (t11 - t12 < TAU_) {
                const float thr = t11 - 2.0f * TAU_;
                float best = -3.4e38f; int bi = 0;
                for (int i = 0; i < 32; i++) {
                    const float gi = gp1[i];
                    if (v[i] + gi >= thr) {
                        const float vex = exact_logit(
                            xr, W1g + (size_t)(bn + g4*32 + i) * E_, cb[g4*32 + i]);
                        const float cand = vex + gi;
                        if (cand > best) { best = cand; bi = i; }
                    }
                }
                a1 = bi;
            }
            if (t21 - t22 < TAU_) {
                const float thr = t21 - 2.0f * TAU_;
                float best = -3.4e38f; int bi = 0;
                for (int i = 0; i < 32; i++) {
                    const float gi = gp2[i];
                    if (v[i] + gi >= thr) {
                        const float vex = exact_logit(
                            xr, W1g + (size_t)(bn + g4*32 + i) * E_, cb[g4*32 + i]);
                        const float cand = vex + gi;
                        if (cand > best) { best = cand; bi = i; }
                    }
                }
                a2 = bi;
            }
        }

        const float w  = w_interp[(size_t)token * G_ + gid];
        const float u  = u_interp[(size_t)token * G_ + gid];
        const bool  ui = (u < 1.0f);              // INTERP_PROB = 1.0
        const float wa = ui ? w : 1.0f;
        const float wb = ui ? (1.0f - w) : 0.0f;

        float* sp = outSampled + (size_t)token * C_ + bn + g4 * 32;
#pragma unroll
        for (int q = 0; q < 8; q++) {
            float o[4];
#pragma unroll
            for (int k = 0; k < 4; k++) {
                const int i = q * 4 + k;
                float val = 0.0f;
                if (i == a1) val += wa;
                if (i == a2) val += wb;
                o[k] = val;
            }
            *(float4*)(sp + q * 4) = make_float4(o[0], o[1], o[2], o[3]);
        }
        g_idx[(size_t)token * G_ + gid] =
            (unsigned)a1 | ((unsigned)a2 << 8) | (ui ? 0x10000u : 0u);
    }
}

// ---------------- kernel 4: sparse projection + LayerNorm -> pos, neg -------
__global__ __launch_bounds__(128)
void proj_ln_kernel(const float* __restrict__ w_interp,
                    const float* __restrict__ b2,
                    const float* __restrict__ gamma,
                    const float* __restrict__ beta,
                    float* __restrict__ outPos,
                    float* __restrict__ outNeg) {
    const int tok = blockIdx.x;
    const int tid = threadIdx.x;
    __shared__ unsigned sidx[32];
    __shared__ float    sw[32];
    __shared__ float    red1[4], red2[4];

    if (tid < 32) {
        sidx[tid] = g_idx[(size_t)tok * G_ + tid];
        sw[tid]   = w_interp[(size_t)tok * G_ + tid];
    }
    __syncthreads();

    const int e4 = tid * 4;
    float4 bb = *(const float4*)(b2 + e4);
    float hx = bb.x, hy = bb.y, hz = bb.z, hw = bb.w;

#pragma unroll
    for (int g = 0; g < 32; g++) {
        const unsigned p = sidx[g];
        const float w = sw[g];
        const bool ui = (p & 0x10000u) != 0u;
        const int a1 = p & 255;
        const int a2 = (p >> 8) & 255;
        const float wa = ui ? w : 1.0f;
        const float wb = ui ? (1.0f - w) : 0.0f;
        const float4 r1 = *(const float4*)&g_W2T[(size_t)(g * CG_ + a1) * E_ + e4];
        const float4 r2 = *(const float4*)&g_W2T[(size_t)(g * CG_ + a2) * E_ + e4];
        hx += wa * r1.x + wb * r2.x;
        hy += wa * r1.y + wb * r2.y;
        hz += wa * r1.z + wb * r2.z;
        hw += wa * r1.w + wb * r2.w;
    }

    float s1 = hx + hy + hz + hw;
    float s2 = hx * hx + hy * hy + hz * hz + hw * hw;
#pragma unroll
    for (int off = 16; off > 0; off >>= 1) {
        s1 += __shfl_xor_sync(0xFFFFFFFFu, s1, off);
        s2 += __shfl_xor_sync(0xFFFFFFFFu, s2, off);
    }
    const int wid = tid >> 5, lid = tid & 31;
    if (lid == 0) { red1[wid] = s1; red2[wid] = s2; }
    __syncthreads();
    s1 = red1[0] + red1[1] + red1[2] + red1[3];
    s2 = red2[0] + red2[1] + red2[2] + red2[3];

    const float mean = s1 * (1.0f / (float)E_);
    const float var  = s2 * (1.0f / (float)E_) - mean * mean;
    const float rstd = rsqrtf(var + 1e-5f);

    const float4 gm = *(const float4*)(gamma + e4);
    const float4 bt = *(const float4*)(beta + e4);
    float4 o;
    o.x = (hx - mean) * rstd * gm.x + bt.x;
    o.y = (hy - mean) * rstd * gm.y + bt.y;
    o.z = (hz - mean) * rstd * gm.z + bt.z;
    o.w = (hw - mean) * rstd * gm.w + bt.w;

    *(float4*)(outPos + (size_t)tok * E_ + e4) = o;
    *(float4*)(outNeg + (size_t)tok * E_ + e4) = o;   // rev fwd == sampled
}

// ---------------- launch ----------------
extern "C" void kernel_launch(void* const* d_in, const int* in_sizes, int n_in,
                              void* d_out, int out_size) {
    const float* x     = (const float*)d_in[0];
    const float* W1    = (const float*)d_in[1];
    const float* b1    = (const float*)d_in[2];
    const float* coff  = (const float*)d_in[3];
    const float* W2    = (const float*)d_in[4];
    const float* b2    = (const float*)d_in[5];
    const float* gamma = (const float*)d_in[6];
    const float* beta  = (const float*)d_in[7];
    const float* g1    = (const float*)d_in[8];
    const float* g2    = (const float*)d_in[9];
    const float* wi    = (const float*)d_in[10];
    const float* ui    = (const float*)d_in[11];

    float* out        = (float*)d_out;
    float* outSampled = out;
    float* outSoft    = out + (size_t)M_ * C_;
    float* outPos     = out + 2 * (size_t)M_ * C_;
    float* outNeg     = outPos + (size_t)M_ * E_;

    cudaFuncSetAttribute(gemm_fused_kernel,
                         cudaFuncAttributeMaxDynamicSharedMemorySize, SMEM_BYTES);

    transpose_kernel<<<dim3(C_ / 32, E_ / 32), dim3(32, 8)>>>(W2);
    split_kernel<<<(int)(((size_t)R_ * E_) / 8 / 256), 256>>>(x, W1);
    gemm_fused_kernel<<<dim3(C_ / 128, M_ / 128), 256, SMEM_BYTES>>>(
        x, W1, b1, coff, g1, g2, wi, ui, outSampled, outSoft);
    proj_ln_kernel<<<M_, 128>>>(wi, b2, gamma, beta, outPos, outNeg);
}